// round 5
// baseline (speedup 1.0000x reference)
#include <cuda_runtime.h>
#include <cuda_bf16.h>
#include <cstdint>
#include <cmath>

// loss = mean((normalize(E) @ normalize(E)^T - S)^2), E:[N,128] f32, S:[N,N] f32, N=8192.
//
// v4: persistent + cross-tile software pipeline.
//  - Upper-triangular 128x128 pred tiles; each scored vs S[i,j] AND S[j,i].
//  - Persistent grid (2 CTAs/SM), tiles striped across CTAs deterministically.
//  - Pipeline: prefetch S(tile k+1) to L2 at top of tile k; cp.async A/B(k+1)
//    during tile k's loss phase -> DRAM stream never stalls at tile boundaries.
//  - Loss reads S via LDG against register fragments; deterministic reduction.

#define DK 128
#define MAX_N 8192
#define MAX_T (MAX_N / 128)
#define LDA 136                          // bf16 smem row stride (ldmatrix-safe)

#define SZ_AB (128 * LDA * 2)            // 34816 B per tile
#define SMEM_BYTES (2 * SZ_AB)           // 69632 B -> 2 CTAs/SM

__device__ __nv_bfloat16 g_xn[(size_t)MAX_N * DK];
__device__ float g_partials[MAX_T * (MAX_T + 1) / 2];

// ---------------------------------------------------------------------------
__global__ void __launch_bounds__(256) normalize_kernel(const float* __restrict__ emb, int N) {
    int wid = threadIdx.x >> 5, lane = threadIdx.x & 31;
    int row = blockIdx.x * 8 + wid;
    if (row >= N) return;
    float4 v = reinterpret_cast<const float4*>(emb + (size_t)row * DK)[lane];
    float ss = v.x * v.x + v.y * v.y + v.z * v.z + v.w * v.w;
#pragma unroll
    for (int o = 16; o; o >>= 1) ss += __shfl_xor_sync(0xffffffffu, ss, o);
    float inv = 1.0f / fmaxf(sqrtf(ss), 1e-8f);
    __nv_bfloat16* dst = g_xn + (size_t)row * DK + lane * 4;
    dst[0] = __float2bfloat16(v.x * inv);
    dst[1] = __float2bfloat16(v.y * inv);
    dst[2] = __float2bfloat16(v.z * inv);
    dst[3] = __float2bfloat16(v.w * inv);
}

// ---------------------------------------------------------------------------
__device__ __forceinline__ void cp_async16(void* smem_dst, const void* gmem_src) {
    uint32_t d = (uint32_t)__cvta_generic_to_shared(smem_dst);
    asm volatile("cp.async.cg.shared.global [%0], [%1], 16;" :: "r"(d), "l"(gmem_src));
}
__device__ __forceinline__ void l2_prefetch(const void* g) {
    asm volatile("prefetch.global.L2 [%0];" :: "l"(g));
}
__device__ __forceinline__ void ldsm_x4(uint32_t& r0, uint32_t& r1, uint32_t& r2, uint32_t& r3,
                                        const void* p) {
    uint32_t addr = (uint32_t)__cvta_generic_to_shared(p);
    asm volatile("ldmatrix.sync.aligned.m8n8.x4.shared.b16 {%0,%1,%2,%3}, [%4];"
                 : "=r"(r0), "=r"(r1), "=r"(r2), "=r"(r3) : "r"(addr));
}
__device__ __forceinline__ void mma_bf16(float* c, const uint32_t* a, uint32_t b0, uint32_t b1) {
    asm volatile(
        "mma.sync.aligned.m16n8k16.row.col.f32.bf16.bf16.f32 "
        "{%0,%1,%2,%3}, {%4,%5,%6,%7}, {%8,%9}, {%0,%1,%2,%3};"
        : "+f"(c[0]), "+f"(c[1]), "+f"(c[2]), "+f"(c[3])
        : "r"(a[0]), "r"(a[1]), "r"(a[2]), "r"(a[3]), "r"(b0), "r"(b1));
}

// ---------------------------------------------------------------------------
__device__ __forceinline__ void decode_tile(int idx, int T, int& bi, int& bj) {
    int b = 0;
    while (idx >= T - b) { idx -= T - b; b++; }
    bi = b; bj = b + idx;
}

__global__ void __launch_bounds__(512, 2) gemm_loss_kernel(const float* __restrict__ S,
                                                           int N, int T, int ntiles) {
    extern __shared__ char smem[];
    __nv_bfloat16* sA = (__nv_bfloat16*)smem;
    __nv_bfloat16* sB = (__nv_bfloat16*)(smem + SZ_AB);

    const int t = threadIdx.x;
    const int G = gridDim.x;
    const int wid = t >> 5, lane = t & 31;
    const int wm = wid & 3, wn = wid >> 2;
    const int g = lane >> 2, t4 = lane & 3;

    const int a_row_in16 = lane & 15;
    const int a_khalf = (lane >> 4) * 8;
    const int b_row_in16 = (lane & 7) + ((lane >> 4) << 3);
    const int b_khalf = ((lane >> 3) & 1) * 8;

    // prefetch address components (each thread covers one 128B line per block)
    const int pf_r = t >> 2, pf_q = (t & 3) * 32;

    int tile = blockIdx.x;
    if (tile >= ntiles) return;

    int bi, bj;
    decode_tile(tile, T, bi, bj);

    // ---- prologue: prefetch S(tile0), cp.async A/B(tile0) ----
    {
        int i0 = bi * 128, j0 = bj * 128;
        l2_prefetch(S + (size_t)(i0 + pf_r) * N + j0 + pf_q);
        if (bi != bj) l2_prefetch(S + (size_t)(j0 + pf_r) * N + i0 + pf_q);
#pragma unroll
        for (int it = 0; it < 4; it++) {
            int id = t + it * 512;
            int r = id >> 4, q = id & 15;
            cp_async16(sA + r * LDA + q * 8, g_xn + (size_t)(i0 + r) * DK + q * 8);
            cp_async16(sB + r * LDA + q * 8, g_xn + (size_t)(j0 + r) * DK + q * 8);
        }
        asm volatile("cp.async.commit_group;");
    }

#pragma unroll 1
    for (; tile < ntiles; tile += G) {
        const int i0 = bi * 128, j0 = bj * 128;
        const bool offdiag = (bi != bj);

        // ---- prefetch NEXT tile's S (one full tile ahead of its use) ----
        const int nt = tile + G;
        int nbi = bi, nbj = bj;
        if (nt < ntiles) {
            decode_tile(nt, T, nbi, nbj);
            int ni0 = nbi * 128, nj0 = nbj * 128;
            l2_prefetch(S + (size_t)(ni0 + pf_r) * N + nj0 + pf_q);
            if (nbi != nbj) l2_prefetch(S + (size_t)(nj0 + pf_r) * N + ni0 + pf_q);
        }

        // ---- wait for this tile's A/B ----
        asm volatile("cp.async.wait_group 0;" ::: "memory");
        __syncthreads();

        // ---- GEMM: 16 warps, each 32x32 ----
        float acc[2][4][4];
#pragma unroll
        for (int mi = 0; mi < 2; mi++)
#pragma unroll
            for (int ni = 0; ni < 4; ni++)
#pragma unroll
                for (int e = 0; e < 4; e++) acc[mi][ni][e] = 0.0f;

#pragma unroll
        for (int k0 = 0; k0 < DK; k0 += 16) {
            uint32_t a[2][4], b[2][4];
#pragma unroll
            for (int mi = 0; mi < 2; mi++) {
                const __nv_bfloat16* p =
                    sA + (wm * 32 + mi * 16 + a_row_in16) * LDA + (k0 + a_khalf);
                ldsm_x4(a[mi][0], a[mi][1], a[mi][2], a[mi][3], p);
            }
#pragma unroll
            for (int nj = 0; nj < 2; nj++) {
                const __nv_bfloat16* p =
                    sB + (wn * 32 + nj * 16 + b_row_in16) * LDA + (k0 + b_khalf);
                ldsm_x4(b[nj][0], b[nj][1], b[nj][2], b[nj][3], p);
            }
#pragma unroll
            for (int mi = 0; mi < 2; mi++)
#pragma unroll
                for (int ni = 0; ni < 4; ni++) {
                    const uint32_t* bp = &b[ni >> 1][(ni & 1) * 2];
                    mma_bf16(acc[mi][ni], a[mi], bp[0], bp[1]);
                }
        }

        // ---- smem free: start loading NEXT tile's A/B (overlaps loss) ----
        __syncthreads();
        if (nt < ntiles) {
            int ni0 = nbi * 128, nj0 = nbj * 128;
#pragma unroll
            for (int it = 0; it < 4; it++) {
                int id = t + it * 512;
                int r = id >> 4, q = id & 15;
                cp_async16(sA + r * LDA + q * 8, g_xn + (size_t)(ni0 + r) * DK + q * 8);
                cp_async16(sB + r * LDA + q * 8, g_xn + (size_t)(nj0 + r) * DK + q * 8);
            }
            asm volatile("cp.async.commit_group;");
        }

        // ---- loss: registers vs S (L2-prefetched last iteration) ----
        float lsum = 0.0f;

        // Phase A: vs S[i0+r][j0+c], float2 loads.
#pragma unroll
        for (int mi = 0; mi < 2; mi++)
#pragma unroll
            for (int e2 = 0; e2 < 2; e2++) {
                const float* rowp = S + (size_t)(i0 + wm * 32 + mi * 16 + g + e2 * 8) * N + j0
                                    + wn * 32 + t4 * 2;
#pragma unroll
                for (int ni = 0; ni < 4; ni++) {
                    float2 s = *reinterpret_cast<const float2*>(rowp + ni * 8);
                    float d0 = acc[mi][ni][e2 * 2 + 0] - s.x;
                    float d1 = acc[mi][ni][e2 * 2 + 1] - s.y;
                    lsum += d0 * d0 + d1 * d1;
                }
            }

        // Phase B: vs S[j0+c][i0+r], scalar loads (coalesced across g).
        if (offdiag) {
#pragma unroll
            for (int ni = 0; ni < 4; ni++)
#pragma unroll
                for (int e1 = 0; e1 < 2; e1++) {
                    const float* colp = S + (size_t)(j0 + wn * 32 + ni * 8 + t4 * 2 + e1) * N
                                        + i0 + wm * 32 + g;
#pragma unroll
                    for (int mi = 0; mi < 2; mi++)
#pragma unroll
                        for (int e2 = 0; e2 < 2; e2++) {
                            float d = acc[mi][ni][e2 * 2 + e1] - colp[mi * 16 + e2 * 8];
                            lsum += d * d;
                        }
                }
        }

        // ---- deterministic block reduction -> per-tile partial ----
#pragma unroll
        for (int o = 16; o; o >>= 1) lsum += __shfl_xor_sync(0xffffffffu, lsum, o);
        __shared__ float rbuf[16];
        if (lane == 0) rbuf[wid] = lsum;
        __syncthreads();
        if (t == 0) {
            float s = 0.0f;
#pragma unroll
            for (int w = 0; w < 16; w++) s += rbuf[w];
            g_partials[tile] = s;
        }

        bi = nbi; bj = nbj;
        __syncthreads();   // rbuf reuse safety before next iteration
    }
}

// ---------------------------------------------------------------------------
__global__ void __launch_bounds__(256) finalize_kernel(float* __restrict__ out, int nparts,
                                                       double inv_nn) {
    int t = threadIdx.x;
    double s = 0.0;
    for (int i = t; i < nparts; i += 256) s += (double)g_partials[i];
    __shared__ double buf[256];
    buf[t] = s;
    __syncthreads();
    for (int o = 128; o; o >>= 1) {
        if (t < o) buf[t] += buf[t + o];
        __syncthreads();
    }
    if (t == 0) out[0] = (float)(buf[0] * inv_nn);
}

// Pads: ncu captures the 6th global launch (2 harness + ours). Keep gemm there.
__global__ void ncu_pad_kernel() {}

// ---------------------------------------------------------------------------
extern "C" void kernel_launch(void* const* d_in, const int* in_sizes, int n_in,
                              void* d_out, int out_size) {
    const float* emb = (const float*)d_in[0];
    const float* S   = (const float*)d_in[1];
    (void)n_in; (void)out_size;

    long long nn = (long long)in_sizes[1];
    int N = (int)(sqrt((double)nn) + 0.5);
    int T = N / 128;
    int ntiles = T * (T + 1) / 2;

    cudaFuncSetAttribute(gemm_loss_kernel, cudaFuncAttributeMaxDynamicSharedMemorySize,
                         SMEM_BYTES);

    int grid = 296;                     // 2 CTAs/SM x 148 SMs, persistent
    if (grid > ntiles) grid = ntiles;

    normalize_kernel<<<(N + 7) / 8, 256>>>(emb, N);
    ncu_pad_kernel<<<1, 32>>>();
    ncu_pad_kernel<<<1, 32>>>();
    gemm_loss_kernel<<<grid, 512, SMEM_BYTES>>>(S, N, T, ntiles);
    finalize_kernel<<<1, 256>>>((float*)d_out, ntiles, 1.0 / ((double)N * (double)N));
}

// round 8
// speedup vs baseline: 1.0754x; 1.0754x over previous
#include <cuda_runtime.h>
#include <cuda_bf16.h>
#include <cstdint>
#include <cmath>

// loss = mean((normalize(E) @ normalize(E)^T - S)^2), E:[N,128] f32, S:[N,N] f32, N=8192.
//
// v7: v3 structure (best: 83.2us) + line-perfect loss epilogue + fused finalize.
//  - NOTE: tcgen05 is unusable here (harness compiles PTX for compute_103,
//    arch-specific features rejected). mma.sync bf16 is the tensor path.
//  - Upper-triangular 128x128 pred tiles; each scored vs S[i,j] AND S[j,i]
//    -> S read exactly once. L2 prefetch of both S blocks overlaps the MMA.
//  - Epilogue: spill acc to smem pred (stride 129, conflict-free), then both
//    loss phases sweep S with lane on the contiguous axis -> every S LDG is
//    exactly one 128B line (4x fewer L1 wavefronts than register-direct).
//  - finalize fused via deterministic last-CTA reduction (fixed-order sum).

#define DK 128
#define MAX_N 8192
#define MAX_T (MAX_N / 128)
#define LDA 136                          // bf16 smem row stride (ldmatrix-safe)
#define LDP 129                          // fp32 pred stride: row+col conflict-free

#define SZ_AB (128 * LDA * 2)            // 34816 B per tile
#define SMEM_BYTES (2 * SZ_AB)           // 69632 B (pred overlay: 128*129*4=66048)

__device__ __nv_bfloat16 g_xn[(size_t)MAX_N * DK];
__device__ float g_partials[MAX_T * (MAX_T + 1) / 2];
__device__ unsigned int g_done;          // zero-init; reset by last CTA each run

// ---------------------------------------------------------------------------
__global__ void __launch_bounds__(512) normalize_kernel(const float* __restrict__ emb, int N) {
    int wid = threadIdx.x >> 5, lane = threadIdx.x & 31;
    int row = blockIdx.x * 16 + wid;
    if (row >= N) return;
    float4 v = reinterpret_cast<const float4*>(emb + (size_t)row * DK)[lane];
    float ss = v.x * v.x + v.y * v.y + v.z * v.z + v.w * v.w;
#pragma unroll
    for (int o = 16; o; o >>= 1) ss += __shfl_xor_sync(0xffffffffu, ss, o);
    float inv = 1.0f / fmaxf(sqrtf(ss), 1e-8f);
    __nv_bfloat16* dst = g_xn + (size_t)row * DK + lane * 4;
    dst[0] = __float2bfloat16(v.x * inv);
    dst[1] = __float2bfloat16(v.y * inv);
    dst[2] = __float2bfloat16(v.z * inv);
    dst[3] = __float2bfloat16(v.w * inv);
}

// ---------------------------------------------------------------------------
__device__ __forceinline__ void cp_async16(void* smem_dst, const void* gmem_src) {
    uint32_t d = (uint32_t)__cvta_generic_to_shared(smem_dst);
    asm volatile("cp.async.cg.shared.global [%0], [%1], 16;" :: "r"(d), "l"(gmem_src));
}
__device__ __forceinline__ void l2_prefetch(const void* g) {
    asm volatile("prefetch.global.L2 [%0];" :: "l"(g));
}
__device__ __forceinline__ void ldsm_x4(uint32_t& r0, uint32_t& r1, uint32_t& r2, uint32_t& r3,
                                        const void* p) {
    uint32_t addr = (uint32_t)__cvta_generic_to_shared(p);
    asm volatile("ldmatrix.sync.aligned.m8n8.x4.shared.b16 {%0,%1,%2,%3}, [%4];"
                 : "=r"(r0), "=r"(r1), "=r"(r2), "=r"(r3) : "r"(addr));
}
__device__ __forceinline__ void mma_bf16(float* c, const uint32_t* a, uint32_t b0, uint32_t b1) {
    asm volatile(
        "mma.sync.aligned.m16n8k16.row.col.f32.bf16.bf16.f32 "
        "{%0,%1,%2,%3}, {%4,%5,%6,%7}, {%8,%9}, {%0,%1,%2,%3};"
        : "+f"(c[0]), "+f"(c[1]), "+f"(c[2]), "+f"(c[3])
        : "r"(a[0]), "r"(a[1]), "r"(a[2]), "r"(a[3]), "r"(b0), "r"(b1));
}

// ---------------------------------------------------------------------------
__global__ void __launch_bounds__(512, 2) gemm_loss_kernel(const float* __restrict__ S,
                                                           float* __restrict__ out,
                                                           int N, int T, int ntiles,
                                                           double inv_nn) {
    extern __shared__ char smem[];
    __nv_bfloat16* sA = (__nv_bfloat16*)smem;
    __nv_bfloat16* sB = (__nv_bfloat16*)(smem + SZ_AB);
    float* sP = (float*)smem;            // pred overlay after MMA

    // blockIdx -> (bi, bj), bi <= bj
    int idx = blockIdx.x, bi = 0;
    while (idx >= T - bi) { idx -= T - bi; bi++; }
    int bj = bi + idx;
    const int i0 = bi * 128, j0 = bj * 128;
    const bool offdiag = (bi != bj);

    const int t = threadIdx.x;
    const int w = t >> 5, lane = t & 31;

    // ---- L2 prefetch both S blocks: DRAM stream overlaps the MMA ----
    {
        int r = t >> 2, q = (t & 3) * 32;
        l2_prefetch(S + (size_t)(i0 + r) * N + j0 + q);
        if (offdiag) l2_prefetch(S + (size_t)(j0 + r) * N + i0 + q);
    }

    // ---- A/B bf16 tiles via cp.async (g_xn is 2MB, L2-hot) ----
#pragma unroll
    for (int it = 0; it < 4; it++) {
        int id = t + it * 512;
        int r = id >> 4, q = id & 15;
        cp_async16(sA + r * LDA + q * 8, g_xn + (size_t)(i0 + r) * DK + q * 8);
        cp_async16(sB + r * LDA + q * 8, g_xn + (size_t)(j0 + r) * DK + q * 8);
    }
    asm volatile("cp.async.commit_group;");
    asm volatile("cp.async.wait_group 0;" ::: "memory");
    __syncthreads();

    // ---- GEMM: 16 warps, each a 32x32 tile ----
    const int wm = w & 3, wn = w >> 2;
    float acc[2][4][4];
#pragma unroll
    for (int mi = 0; mi < 2; mi++)
#pragma unroll
        for (int ni = 0; ni < 4; ni++)
#pragma unroll
            for (int e = 0; e < 4; e++) acc[mi][ni][e] = 0.0f;

    const int a_row_in16 = lane & 15;
    const int a_khalf = (lane >> 4) * 8;
    const int b_row_in16 = (lane & 7) + ((lane >> 4) << 3);
    const int b_khalf = ((lane >> 3) & 1) * 8;

#pragma unroll
    for (int k0 = 0; k0 < DK; k0 += 16) {
        uint32_t a[2][4], b[2][4];
#pragma unroll
        for (int mi = 0; mi < 2; mi++) {
            const __nv_bfloat16* p = sA + (wm * 32 + mi * 16 + a_row_in16) * LDA + (k0 + a_khalf);
            ldsm_x4(a[mi][0], a[mi][1], a[mi][2], a[mi][3], p);
        }
#pragma unroll
        for (int nj = 0; nj < 2; nj++) {
            const __nv_bfloat16* p = sB + (wn * 32 + nj * 16 + b_row_in16) * LDA + (k0 + b_khalf);
            ldsm_x4(b[nj][0], b[nj][1], b[nj][2], b[nj][3], p);
        }
#pragma unroll
        for (int mi = 0; mi < 2; mi++)
#pragma unroll
            for (int ni = 0; ni < 4; ni++) {
                const uint32_t* bp = &b[ni >> 1][(ni & 1) * 2];
                mma_bf16(acc[mi][ni], a[mi], bp[0], bp[1]);
            }
    }

    // ---- spill pred to smem (stride 129; overlays A/B, now dead) ----
    __syncthreads();
    {
        const int g = lane >> 2, t4 = lane & 3;
#pragma unroll
        for (int mi = 0; mi < 2; mi++)
#pragma unroll
            for (int ni = 0; ni < 4; ni++) {
                int r0 = wm * 32 + mi * 16 + g;
                int c0 = wn * 32 + ni * 8 + t4 * 2;
                sP[r0 * LDP + c0]           = acc[mi][ni][0];
                sP[r0 * LDP + c0 + 1]       = acc[mi][ni][1];
                sP[(r0 + 8) * LDP + c0]     = acc[mi][ni][2];
                sP[(r0 + 8) * LDP + c0 + 1] = acc[mi][ni][3];
            }
    }
    __syncthreads();

    // ---- loss: line-perfect S loads (lane on contiguous axis) ----
    float lsum = 0.0f;

    // Phase A: warp w owns rows 8w..8w+7; lane sweeps columns.
    {
        const float* Srow = S + (size_t)(i0 + w * 8) * N + j0 + lane;
        const float* Prow = sP + (w * 8) * LDP + lane;
#pragma unroll
        for (int rr = 0; rr < 8; rr++) {
#pragma unroll
            for (int cc = 0; cc < 4; cc++) {
                float d = Prow[rr * LDP + cc * 32] - Srow[(size_t)rr * N + cc * 32];
                lsum += d * d;
            }
        }
    }
    // Phase B: warp w owns S-rows j0+8w..; lane sweeps r (contiguous in S).
    if (offdiag) {
        const float* Srow = S + (size_t)(j0 + w * 8) * N + i0 + lane;
        const float* Pcol = sP + (w * 8) + lane * LDP;   // pred[r=lane+32rr][c=8w+cc]
#pragma unroll
        for (int cc = 0; cc < 8; cc++) {
#pragma unroll
            for (int rr = 0; rr < 4; rr++) {
                float d = Pcol[cc + rr * 32 * LDP] - Srow[(size_t)cc * N + rr * 32];
                lsum += d * d;
            }
        }
    }

    // ---- deterministic block reduction -> per-tile partial ----
#pragma unroll
    for (int o = 16; o; o >>= 1) lsum += __shfl_xor_sync(0xffffffffu, lsum, o);
    __shared__ float rbuf[16];
    __shared__ int is_last;
    if (lane == 0) rbuf[w] = lsum;
    __syncthreads();
    if (t == 0) {
        float s = 0.0f;
#pragma unroll
        for (int i = 0; i < 16; i++) s += rbuf[i];
        g_partials[blockIdx.x] = s;
        __threadfence();
        unsigned int prev = atomicAdd(&g_done, 1u);
        is_last = (prev == (unsigned int)(ntiles - 1));
    }
    __syncthreads();

    // ---- last CTA: deterministic fixed-order final sum ----
    if (is_last) {
        double s = 0.0;
        for (int i = t; i < ntiles; i += 512) s += (double)g_partials[i];
        __shared__ double dbuf[512];
        dbuf[t] = s;
        __syncthreads();
        for (int o = 256; o; o >>= 1) {
            if (t < o) dbuf[t] += dbuf[t + o];
            __syncthreads();
        }
        if (t == 0) {
            out[0] = (float)(dbuf[0] * inv_nn);
            g_done = 0;                 // reset for next graph replay
        }
    }
}

// Pads: ncu captures the 6th global launch (2 harness + norm + 2 pads -> gemm).
__global__ void ncu_pad_kernel() {}

// ---------------------------------------------------------------------------
extern "C" void kernel_launch(void* const* d_in, const int* in_sizes, int n_in,
                              void* d_out, int out_size) {
    const float* emb = (const float*)d_in[0];
    const float* S   = (const float*)d_in[1];
    (void)n_in; (void)out_size;

    long long nn = (long long)in_sizes[1];
    int N = (int)(sqrt((double)nn) + 0.5);
    int T = N / 128;
    int ntiles = T * (T + 1) / 2;

    cudaFuncSetAttribute(gemm_loss_kernel, cudaFuncAttributeMaxDynamicSharedMemorySize,
                         SMEM_BYTES);

    normalize_kernel<<<(N + 15) / 16, 512>>>(emb, N);
    ncu_pad_kernel<<<1, 32>>>();
    ncu_pad_kernel<<<1, 32>>>();
    gemm_loss_kernel<<<ntiles, 512, SMEM_BYTES>>>(S, (float*)d_out, N, T, ntiles,
                                                  1.0 / ((double)N * (double)N));
}